// round 15
// baseline (speedup 1.0000x reference)
#include <cuda_runtime.h>
#include <math.h>

// Fixed problem shapes
#define Bv   16
#define Cc   256
#define Nn   64
#define NN   4096
#define Ss   128
#define EPSN 1e-12f
#define SCALE 10.0f
#define TPB  512     // 4 teams x 128 threads

typedef unsigned long long ull;

// Packed dual-fp32 FMA / ADD (Blackwell)
#define FFMA2(acc, a, bb) \
    asm("fma.rn.f32x2 %0, %1, %2, %0;" : "+l"(acc) : "l"(a), "l"(bb))
#define FADD2(dst, a, bb) \
    asm("add.rn.f32x2 %0, %1, %2;" : "=l"(dst) : "l"(a), "l"(bb))

__device__ __forceinline__ float f2lo(ull x) {
    return __uint_as_float((unsigned)(x & 0xffffffffu));
}
__device__ __forceinline__ float f2hi(ull x) {
    return __uint_as_float((unsigned)(x >> 32));
}

// ---------------------------------------------------------------------------
// Single fused kernel. Block = 512 thr = 4 teams x 128;
// team = (space sp, channel-half ch); thread owns 2 adjacent columns.
// Sentence prep is fused: warp w handles (space w>>3, sentence w&7) — loads
// the row once, shfl-reduces the norm, and stores normalized duplicated
// pairs {v,v} directly into the staged smem layout (no separate prep
// kernel, no second global read of sentence feats). Mainloop / reduction /
// epilogue are byte-identical to the best-measured R2 kernel: video feats
// read exactly once, plain LDG.64 stream, no masking tricks (both masked
// -load variants measured SLOWER: the kernel is request-paced).
// grid = (16,16), block 512.
// ---------------------------------------------------------------------------
__global__ __launch_bounds__(TPB, 2) void score_kernel(
    const float* __restrict__ vf1,
    const float* __restrict__ vf2,
    const float* __restrict__ sf1,
    const float* __restrict__ sf2,
    const float* __restrict__ mask2d,
    const int*   __restrict__ nums,
    float* __restrict__ out) {

    // 32 KB: phase A = duplicated normalized sentence pairs,
    // idx (spp*256+c)*8+s; phase B = partial scratch ((team-1)*128+ttid)*9+k
    __shared__ ull buf[4096];

    const int tid  = threadIdx.x;
    const int team = tid >> 7;       // 0..3
    const int ttid = tid & 127;
    const int sp   = team >> 1;      // feature space
    const int ch   = team & 1;       // channel half
    const int w    = tid >> 5;       // warp 0..15
    const int lane = tid & 31;
    const int b    = blockIdx.y;
    const int ij0  = blockIdx.x * 256 + 2 * ttid;

    // Per-block sentence range from nums (tiny, L2-cached)
    int start = 0;
    #pragma unroll
    for (int i = 0; i < Bv; i++) start += (i < b) ? nums[i] : 0;
    int end = start + nums[b];
    if (end > Ss) end = Ss;
    if (start >= end) return;        // uniform per block

    const float* vf = (sp == 0) ? vf1 : vf2;
    const ull* __restrict__ v = reinterpret_cast<const ull*>(
        vf + ((size_t)b * Cc + (size_t)ch * 128) * NN + ij0);

    const ull* __restrict__ sb = buf + (size_t)(sp * 256 + ch * 128) * 8;

    for (int cs = start; cs < end; cs += 8) {
        const int cnt = min(8, end - cs);

        // Phase A: warp w = (spp, s) normalizes its sentence row and stores
        // duplicated pairs straight into the staged layout.
        {
            const int s   = w & 7;
            const int spp = w >> 3;
            float x[8];
            float sum = 0.f;
            if (s < cnt) {
                const float* srcrow = (spp ? sf2 : sf1) +
                                      (size_t)(cs + s) * Cc;
                #pragma unroll
                for (int k = 0; k < 8; k++) {
                    x[k] = srcrow[lane + 32 * k];
                    sum += x[k] * x[k];
                }
            } else {
                #pragma unroll
                for (int k = 0; k < 8; k++) x[k] = 0.f;
            }
            #pragma unroll
            for (int o = 16; o; o >>= 1)
                sum += __shfl_xor_sync(0xffffffffu, sum, o);
            const float inv = 1.f / fmaxf(sqrtf(sum), EPSN);
            #pragma unroll
            for (int k = 0; k < 8; k++) {
                const int c = lane + 32 * k;
                const float val = x[k] * inv;
                float2 d = make_float2(val, val);
                buf[(size_t)(spp * 256 + c) * 8 + s] =
                    *reinterpret_cast<ull*>(&d);
            }
        }
        __syncthreads();

        ull acc[8];
        #pragma unroll
        for (int s = 0; s < 8; s++) acc[s] = 0ull;
        ull nrm = 0ull;

        #pragma unroll 4
        for (int c = 0; c < 128; c++) {
            const ull a = v[(size_t)c * (NN / 2)];
            FFMA2(nrm, a, a);
            const ulonglong2* p =
                reinterpret_cast<const ulonglong2*>(sb + c * 8);
            const ulonglong2 q0 = p[0];
            const ulonglong2 q1 = p[1];
            FFMA2(acc[0], a, q0.x); FFMA2(acc[1], a, q0.y);
            FFMA2(acc[2], a, q1.x); FFMA2(acc[3], a, q1.y);
            const ulonglong2 q2 = p[2];
            const ulonglong2 q3 = p[3];
            FFMA2(acc[4], a, q2.x); FFMA2(acc[5], a, q2.y);
            FFMA2(acc[6], a, q3.x); FFMA2(acc[7], a, q3.y);
        }
        __syncthreads();   // done reading sentence smem

        // Phase B: teams 1..3 publish partials
        if (team != 0) {
            ull* r = buf + ((size_t)(team - 1) * 128 + ttid) * 9;
            #pragma unroll
            for (int s = 0; s < 8; s++) r[s] = acc[s];
            r[8] = nrm;
        }
        __syncthreads();

        if (team == 0) {
            const ull* r1 = buf + ((size_t)0 * 128 + ttid) * 9; // sp0, ch1
            const ull* r2 = buf + ((size_t)1 * 128 + ttid) * 9; // sp1, ch0
            const ull* r3 = buf + ((size_t)2 * 128 + ttid) * 9; // sp1, ch1

            ull t1[8], t2[8], n1, n2;
            #pragma unroll
            for (int s = 0; s < 8; s++) {
                FADD2(t1[s], acc[s], r1[s]);
                FADD2(t2[s], r2[s], r3[s]);
            }
            FADD2(n1, nrm, r1[8]);
            FADD2(n2, r2[8], r3[8]);

            const float i1lo = 1.f / fmaxf(sqrtf(f2lo(n1)), EPSN);
            const float i1hi = 1.f / fmaxf(sqrtf(f2hi(n1)), EPSN);
            const float i2lo = 1.f / fmaxf(sqrtf(f2lo(n2)), EPSN);
            const float i2hi = 1.f / fmaxf(sqrtf(f2hi(n2)), EPSN);

            const float2 mv = *reinterpret_cast<const float2*>(mask2d + ij0);
            const float m0 = mv.x, m1 = mv.y;

            for (int s = 0; s < cnt; s++) {
                const size_t srow = (size_t)(cs + s);
                const float lglo = SCALE * (f2lo(t1[s]) * i1lo);
                const float lghi = SCALE * (f2hi(t1[s]) * i1hi);
                *reinterpret_cast<float2*>(out + srow * NN + ij0) =
                    make_float2(lglo, lghi);

                const float ioulo = m0 / (1.f + __expf(-lglo));
                const float iouhi = m1 / (1.f + __expf(-lghi));
                const float conlo =
                    fmaxf((f2lo(t2[s]) * i2lo + 1.f) * 0.5f * m0, 0.f);
                const float conhi =
                    fmaxf((f2hi(t2[s]) * i2hi + 1.f) * 0.5f * m1, 0.f);
                *reinterpret_cast<float2*>(
                    out + (size_t)Ss * NN + srow * NN + ij0) =
                    make_float2(sqrtf(conlo) * ioulo, sqrtf(conhi) * iouhi);
            }
        }
        __syncthreads();   // buf safe to restage
    }
}

// ---------------------------------------------------------------------------
extern "C" void kernel_launch(void* const* d_in, const int* in_sizes, int n_in,
                              void* d_out, int out_size) {
    const float* vf1  = (const float*)d_in[0];
    const float* vf2  = (const float*)d_in[1];
    const float* sf1  = (const float*)d_in[2];
    const float* sf2  = (const float*)d_in[3];
    const float* mask = (const float*)d_in[4];
    const int*   nums = (const int*)d_in[5];
    float* out = (float*)d_out;

    score_kernel<<<dim3(NN / 256, Bv), TPB>>>(vf1, vf2, sf1, sf2, mask,
                                              nums, out);
}

// round 16
// speedup vs baseline: 1.0082x; 1.0082x over previous
#include <cuda_runtime.h>
#include <math.h>

// Fixed problem shapes
#define Bv   16
#define Cc   256
#define Nn   64
#define NN   4096
#define Ss   128
#define EPSN 1e-12f
#define SCALE 10.0f
#define TPB  512     // 4 teams x 128 threads

typedef unsigned long long ull;

// Packed dual-fp32 FMA / ADD (Blackwell)
#define FFMA2(acc, a, bb) \
    asm("fma.rn.f32x2 %0, %1, %2, %0;" : "+l"(acc) : "l"(a), "l"(bb))
#define FADD2(dst, a, bb) \
    asm("add.rn.f32x2 %0, %1, %2;" : "=l"(dst) : "l"(a), "l"(bb))

__device__ __forceinline__ float f2lo(ull x) {
    return __uint_as_float((unsigned)(x & 0xffffffffu));
}
__device__ __forceinline__ float f2hi(ull x) {
    return __uint_as_float((unsigned)(x >> 32));
}

// ---------------------------------------------------------------------------
// Single fused kernel. Block = 512 thr = 4 teams x 128;
// team = (space sp, channel-half ch); thread owns 2 adjacent columns.
// Phase A1: 16 warps shfl-reduce the 16 (space, sentence) inv-norms.
// Phase A2: coalesced staging of duplicated normalized pairs (buf[e] with
// consecutive threads -> conflict-free; R15's warp-direct stores were
// 16-way bank-conflicted and cost ~2.5us).
// Mainloop / reduction / epilogue are byte-identical to the best-measured
// R2 kernel: plain LDG.64 stream on ij0, video feats read exactly once.
// No masked-load tricks (measured slower twice: kernel is request-paced).
// grid = (16,16), block 512, one launch.
// ---------------------------------------------------------------------------
__global__ __launch_bounds__(TPB, 2) void score_kernel(
    const float* __restrict__ vf1,
    const float* __restrict__ vf2,
    const float* __restrict__ sf1,
    const float* __restrict__ sf2,
    const float* __restrict__ mask2d,
    const int*   __restrict__ nums,
    float* __restrict__ out) {

    // 32 KB: phase A = duplicated normalized sentence pairs,
    // idx (spp*256+c)*8+s; phase B = partial scratch ((team-1)*128+ttid)*9+k
    __shared__ ull buf[4096];
    __shared__ float s_inv[16];     // inv norms: spp*8+s

    const int tid  = threadIdx.x;
    const int team = tid >> 7;       // 0..3
    const int ttid = tid & 127;
    const int sp   = team >> 1;      // feature space
    const int ch   = team & 1;       // channel half
    const int w    = tid >> 5;       // warp 0..15
    const int lane = tid & 31;
    const int b    = blockIdx.y;
    const int ij0  = blockIdx.x * 256 + 2 * ttid;

    // Per-block sentence range from nums (tiny, L2-cached)
    int start = 0;
    #pragma unroll
    for (int i = 0; i < Bv; i++) start += (i < b) ? nums[i] : 0;
    int end = start + nums[b];
    if (end > Ss) end = Ss;
    if (start >= end) return;        // uniform per block

    const float* vf = (sp == 0) ? vf1 : vf2;
    const ull* __restrict__ v = reinterpret_cast<const ull*>(
        vf + ((size_t)b * Cc + (size_t)ch * 128) * NN + ij0);

    const ull* __restrict__ sb = buf + (size_t)(sp * 256 + ch * 128) * 8;

    for (int cs = start; cs < end; cs += 8) {
        const int cnt = min(8, end - cs);

        // Phase A1: 16 warps compute sentence inv-norms via shfl
        {
            const int s   = w & 7;
            const int spp = w >> 3;
            float sum = 0.f;
            if (s < cnt) {
                const float* srcrow = (spp ? sf2 : sf1) +
                                      (size_t)(cs + s) * Cc;
                #pragma unroll
                for (int k = 0; k < 8; k++) {
                    const float x = srcrow[lane + 32 * k];
                    sum += x * x;
                }
            }
            #pragma unroll
            for (int o = 16; o; o >>= 1)
                sum += __shfl_xor_sync(0xffffffffu, sum, o);
            if (lane == 0)
                s_inv[w] = 1.f / fmaxf(sqrtf(sum), EPSN);
        }
        __syncthreads();

        // Phase A2: coalesced staging of duplicated normalized pairs
        for (int e = tid; e < 2 * Cc * 8; e += TPB) {
            const int s   = e & 7;
            const int c   = (e >> 3) & (Cc - 1);
            const int spp = e >> 11;
            float val = 0.f;
            if (s < cnt)
                val = (spp ? sf2 : sf1)[(size_t)(cs + s) * Cc + c] *
                      s_inv[spp * 8 + s];
            float2 d = make_float2(val, val);
            buf[e] = *reinterpret_cast<ull*>(&d);
        }
        __syncthreads();

        ull acc[8];
        #pragma unroll
        for (int s = 0; s < 8; s++) acc[s] = 0ull;
        ull nrm = 0ull;

        #pragma unroll 4
        for (int c = 0; c < 128; c++) {
            const ull a = v[(size_t)c * (NN / 2)];
            FFMA2(nrm, a, a);
            const ulonglong2* p =
                reinterpret_cast<const ulonglong2*>(sb + c * 8);
            const ulonglong2 q0 = p[0];
            const ulonglong2 q1 = p[1];
            FFMA2(acc[0], a, q0.x); FFMA2(acc[1], a, q0.y);
            FFMA2(acc[2], a, q1.x); FFMA2(acc[3], a, q1.y);
            const ulonglong2 q2 = p[2];
            const ulonglong2 q3 = p[3];
            FFMA2(acc[4], a, q2.x); FFMA2(acc[5], a, q2.y);
            FFMA2(acc[6], a, q3.x); FFMA2(acc[7], a, q3.y);
        }
        __syncthreads();   // done reading sentence smem

        // Phase B: teams 1..3 publish partials
        if (team != 0) {
            ull* r = buf + ((size_t)(team - 1) * 128 + ttid) * 9;
            #pragma unroll
            for (int s = 0; s < 8; s++) r[s] = acc[s];
            r[8] = nrm;
        }
        __syncthreads();

        if (team == 0) {
            const ull* r1 = buf + ((size_t)0 * 128 + ttid) * 9; // sp0, ch1
            const ull* r2 = buf + ((size_t)1 * 128 + ttid) * 9; // sp1, ch0
            const ull* r3 = buf + ((size_t)2 * 128 + ttid) * 9; // sp1, ch1

            ull t1[8], t2[8], n1, n2;
            #pragma unroll
            for (int s = 0; s < 8; s++) {
                FADD2(t1[s], acc[s], r1[s]);
                FADD2(t2[s], r2[s], r3[s]);
            }
            FADD2(n1, nrm, r1[8]);
            FADD2(n2, r2[8], r3[8]);

            const float i1lo = 1.f / fmaxf(sqrtf(f2lo(n1)), EPSN);
            const float i1hi = 1.f / fmaxf(sqrtf(f2hi(n1)), EPSN);
            const float i2lo = 1.f / fmaxf(sqrtf(f2lo(n2)), EPSN);
            const float i2hi = 1.f / fmaxf(sqrtf(f2hi(n2)), EPSN);

            const float2 mv = *reinterpret_cast<const float2*>(mask2d + ij0);
            const float m0 = mv.x, m1 = mv.y;

            for (int s = 0; s < cnt; s++) {
                const size_t srow = (size_t)(cs + s);
                const float lglo = SCALE * (f2lo(t1[s]) * i1lo);
                const float lghi = SCALE * (f2hi(t1[s]) * i1hi);
                *reinterpret_cast<float2*>(out + srow * NN + ij0) =
                    make_float2(lglo, lghi);

                const float ioulo = m0 / (1.f + __expf(-lglo));
                const float iouhi = m1 / (1.f + __expf(-lghi));
                const float conlo =
                    fmaxf((f2lo(t2[s]) * i2lo + 1.f) * 0.5f * m0, 0.f);
                const float conhi =
                    fmaxf((f2hi(t2[s]) * i2hi + 1.f) * 0.5f * m1, 0.f);
                *reinterpret_cast<float2*>(
                    out + (size_t)Ss * NN + srow * NN + ij0) =
                    make_float2(sqrtf(conlo) * ioulo, sqrtf(conhi) * iouhi);
            }
        }
        __syncthreads();   // buf safe to restage
    }
}

// ---------------------------------------------------------------------------
extern "C" void kernel_launch(void* const* d_in, const int* in_sizes, int n_in,
                              void* d_out, int out_size) {
    const float* vf1  = (const float*)d_in[0];
    const float* vf2  = (const float*)d_in[1];
    const float* sf1  = (const float*)d_in[2];
    const float* sf2  = (const float*)d_in[3];
    const float* mask = (const float*)d_in[4];
    const int*   nums = (const int*)d_in[5];
    float* out = (float*)d_out;

    score_kernel<<<dim3(NN / 256, Bv), TPB>>>(vf1, vf2, sf1, sf2, mask,
                                              nums, out);
}